// round 4
// baseline (speedup 1.0000x reference)
#include <cuda_runtime.h>
#include <cstdint>

// out = IFFT( D .* FFT( A .* x ) ) per row, C = 4096, complex as (re,im) float pairs.
// A, D scale re/im independently (elementwise).
//
// 128 threads per row, 2 lanes per thread held in 64-bit packed registers
// (packing is for memory ops; arithmetic is scalar fp32 underneath).
// 4096 = 16^3: three radix-16 register stages; two shared exchanges per
// direction using 16-byte ulonglong2 {re_pair, im_pair} accesses, strides
// 129 / 9 (conflict-free for 128-bit LDS/STS). Twiddles computed directly
// per k with __sincosf (MUFU pipe) instead of serial cmul power chains.

typedef unsigned long long ull;

#define REV(c) ((((c) & 3) << 2) | ((c) >> 2))

// ---------------- packed helpers (memory layout only) ----------------
__device__ __forceinline__ ull pk(float a, float b){
    ull r; asm("mov.b64 %0, {%1, %2};" : "=l"(r) : "f"(a), "f"(b)); return r;
}
__device__ __forceinline__ void unpk(ull v, float& a, float& b){
    asm("mov.b64 {%0, %1}, %2;" : "=f"(a), "=f"(b) : "l"(v));
}
__device__ __forceinline__ float plo(ull v){ float a,b; unpk(v,a,b); return a; }
__device__ __forceinline__ float phi(ull v){ float a,b; unpk(v,a,b); return b; }
__device__ __forceinline__ ull padd(ull a, ull b){
    ull r; asm("add.rn.f32x2 %0, %1, %2;" : "=l"(r) : "l"(a), "l"(b)); return r;
}
__device__ __forceinline__ ull psub(ull a, ull b){
    ull r; asm("sub.rn.f32x2 %0, %1, %2;" : "=l"(r) : "l"(a), "l"(b)); return r;
}
__device__ __forceinline__ ull pmul(ull a, ull b){
    ull r; asm("mul.rn.f32x2 %0, %1, %2;" : "=l"(r) : "l"(a), "l"(b)); return r;
}
__device__ __forceinline__ ull pfma(ull a, ull b, ull c){
    ull r; asm("fma.rn.f32x2 %0, %1, %2, %3;" : "=l"(r) : "l"(a), "l"(b), "l"(c)); return r;
}
__device__ __forceinline__ ull pneg(ull a){
    ull r; asm("xor.b64 %0, %1, %2;" : "=l"(r) : "l"(a), "l"(0x8000000080000000ULL)); return r;
}
__device__ __forceinline__ ull pklo(ull A, ull B){ return pk(plo(A), plo(B)); }
__device__ __forceinline__ ull pkhi(ull A, ull B){ return pk(phi(A), phi(B)); }

// packed complex multiply: (r,i) *= (wr,wi)
__device__ __forceinline__ void cmulp(ull& r, ull& i, ull wr, ull wi){
    ull t  = pmul(i, wi);
    ull nr = psub(pmul(r, wr), t);
    ull ni = pfma(r, wi, pmul(i, wr));
    r = nr; i = ni;
}
// multiply by -i (DIR<0) / +i (DIR>0)
template<int DIR> __device__ __forceinline__ void muljp(ull& r, ull& i){
    ull t = r;
    if (DIR < 0){ r = i;       i = pneg(t); }
    else        { r = pneg(i); i = t; }
}
// constant twiddle, forward (cr, ci_f); inverse = conjugate
template<int DIR> __device__ __forceinline__ void cmulc(ull& r, ull& i, float cr, float ci_f){
    const float ci = (DIR < 0) ? ci_f : -ci_f;
    cmulp(r, i, pk(cr, cr), pk(ci, ci));
}

#define TC1 0.92387953251128674f
#define TS1 0.38268343236508978f
#define TC2 0.70710678118654752f

template<int DIR>
__device__ __forceinline__ void fft4p(ull& r0, ull& i0, ull& r1, ull& i1,
                                      ull& r2, ull& i2, ull& r3, ull& i3){
    ull t0r = padd(r0, r2), t0i = padd(i0, i2);
    ull t1r = psub(r0, r2), t1i = psub(i0, i2);
    ull t2r = padd(r1, r3), t2i = padd(i1, i3);
    ull t3r, t3i;
    if (DIR < 0){ t3r = psub(i1, i3); t3i = psub(r3, r1); }
    else        { t3r = psub(i3, i1); t3i = psub(r1, r3); }
    r0 = padd(t0r, t2r); i0 = padd(t0i, t2i);
    r2 = psub(t0r, t2r); i2 = psub(t0i, t2i);
    r1 = padd(t1r, t3r); i1 = padd(t1i, t3i);
    r3 = psub(t1r, t3r); i3 = psub(t1i, t3i);
}

// 16-point DFT, natural slots in -> output c at slot REV(c)
template<int DIR>
__device__ __forceinline__ void fft16_nat_p(ull re[16], ull im[16]){
    fft4p<DIR>(re[0],im[0], re[4],im[4], re[8], im[8],  re[12],im[12]);
    fft4p<DIR>(re[1],im[1], re[5],im[5], re[9], im[9],  re[13],im[13]);
    fft4p<DIR>(re[2],im[2], re[6],im[6], re[10],im[10], re[14],im[14]);
    fft4p<DIR>(re[3],im[3], re[7],im[7], re[11],im[11], re[15],im[15]);
    cmulc<DIR>(re[5], im[5],  TC1, -TS1);
    cmulc<DIR>(re[9], im[9],  TC2, -TC2);
    cmulc<DIR>(re[13],im[13], TS1, -TC1);
    cmulc<DIR>(re[6], im[6],  TC2, -TC2);
    muljp<DIR>(re[10],im[10]);
    cmulc<DIR>(re[14],im[14],-TC2, -TC2);
    cmulc<DIR>(re[7], im[7],  TS1, -TC1);
    cmulc<DIR>(re[11],im[11],-TC2, -TC2);
    cmulc<DIR>(re[15],im[15],-TC1,  TS1);
    fft4p<DIR>(re[0], im[0],  re[1], im[1],  re[2], im[2],  re[3], im[3]);
    fft4p<DIR>(re[4], im[4],  re[5], im[5],  re[6], im[6],  re[7], im[7]);
    fft4p<DIR>(re[8], im[8],  re[9], im[9],  re[10],im[10], re[11],im[11]);
    fft4p<DIR>(re[12],im[12], re[13],im[13], re[14],im[14], re[15],im[15]);
}

// 16-point DFT, input logical a at slot REV(a) -> natural output slots
template<int DIR>
__device__ __forceinline__ void fft16_rev_p(ull re[16], ull im[16]){
    fft4p<DIR>(re[0], im[0],  re[1], im[1],  re[2], im[2],  re[3], im[3]);
    fft4p<DIR>(re[4], im[4],  re[5], im[5],  re[6], im[6],  re[7], im[7]);
    fft4p<DIR>(re[8], im[8],  re[9], im[9],  re[10],im[10], re[11],im[11]);
    fft4p<DIR>(re[12],im[12], re[13],im[13], re[14],im[14], re[15],im[15]);
    cmulc<DIR>(re[5], im[5],  TC1, -TS1);
    cmulc<DIR>(re[6], im[6],  TC2, -TC2);
    cmulc<DIR>(re[7], im[7],  TS1, -TC1);
    cmulc<DIR>(re[9], im[9],  TC2, -TC2);
    muljp<DIR>(re[10],im[10]);
    cmulc<DIR>(re[11],im[11],-TC2, -TC2);
    cmulc<DIR>(re[13],im[13], TS1, -TC1);
    cmulc<DIR>(re[14],im[14],-TC2, -TC2);
    cmulc<DIR>(re[15],im[15],-TC1,  TS1);
    fft4p<DIR>(re[0],im[0], re[4],im[4], re[8], im[8],  re[12],im[12]);
    fft4p<DIR>(re[1],im[1], re[5],im[5], re[9], im[9],  re[13],im[13]);
    fft4p<DIR>(re[2],im[2], re[6],im[6], re[10],im[10], re[14],im[14]);
    fft4p<DIR>(re[3],im[3], re[7],im[7], re[11],im[11], re[15],im[15]);
}

// Direct twiddles: apply e^{i*k*th_lane} to v[slot(k)], k=1..15.
// Pass th pre-signed (negative for forward): sin(-a) = -sin(a), cos unchanged.
// Each k: 2 FMULs + 4 MUFU (independent across k -> no dep chain, idle SFU pipe).
template<int RV>
__device__ __forceinline__ void twiddle_direct(ull re[16], ull im[16], float th0, float th1){
    #pragma unroll
    for (int k = 1; k < 16; ++k){
        float s0, c0, s1, c1;
        __sincosf((float)k * th0, &s0, &c0);
        __sincosf((float)k * th1, &s1, &c1);
        const int slot = RV ? REV(k) : k;
        cmulp(re[slot], im[slot], pk(c0, c1), pk(s0, s1));
    }
}

#define S1R 129   // pair-row stride (16B units); conflict-free for LDS/STS.128
#define S2R 9
#define D4096 1.5339807878856412e-3f   // 2*pi/4096
#define D256  2.4543692606170259e-2f   // 2*pi/256
#define INV_N (1.0f / 4096.0f)

__global__ void __launch_bounds__(128) afdf_fft4_kernel(
    const float4* __restrict__ x4,
    const float4* __restrict__ A4,
    const float2* __restrict__ D2,
    float2* __restrict__ out2)
{
    // shared scratch, reused: S1 = 16 rows x 129 entries; S2 = 256 rows x 9 entries
    // each entry = 16B {re_pair, im_pair}
    __shared__ ulonglong2 sbuf[256 * S2R];        // 2304 * 16B = 36,864 B
    ulonglong2* const s1 = sbuf;                  // 16*129 = 2064 entries
    ulonglong2* const s2 = sbuf;                  // 256*9  = 2304 entries

    const int t  = threadIdx.x;        // 0..127
    const int c1 = t & 15;
    const int u  = t >> 4;             // 0..7
    const size_t rb4 = (size_t)blockIdx.x * 2048;   // row base in float4 units
    const size_t rb2 = (size_t)blockIdx.x * 4096;   // row base in float2 units

    ull re[16], im[16];

    // ---- load x, apply A; lanes = points m=(2t, 2t+1) ----
    #pragma unroll
    for (int a = 0; a < 16; ++a){
        const float4 xv = x4[rb4 + 128 * a + t];
        const float4 av = A4[128 * a + t];
        re[a] = pmul(pk(xv.x, xv.z), pk(av.x, av.z));
        im[a] = pmul(pk(xv.y, xv.w), pk(av.y, av.w));
    }

    // ================= forward =================
    fft16_nat_p<-1>(re, im);
    twiddle_direct<1>(re, im, -(float)(2*t) * D4096, -(float)(2*t + 1) * D4096);
    #pragma unroll
    for (int c = 0; c < 16; ++c){
        s1[c * S1R + t] = make_ulonglong2(re[REV(c)], im[REV(c)]);
    }
    __syncthreads();
    // stage 2: lanes = (b2 = 2u, 2u+1), iterate a2 (m = 16*a2 + b2)
    #pragma unroll
    for (int a2 = 0; a2 < 16; ++a2){
        const ulonglong2 v = s1[c1 * S1R + 8 * a2 + u];
        re[a2] = v.x; im[a2] = v.y;
    }
    fft16_nat_p<-1>(re, im);
    twiddle_direct<1>(re, im, -(float)(2*u) * D256, -(float)(2*u + 1) * D256);
    __syncthreads();
    #pragma unroll
    for (int c2 = 0; c2 < 16; ++c2){
        s2[(16 * c2 + c1) * S2R + u] = make_ulonglong2(re[REV(c2)], im[REV(c2)]);
    }
    __syncthreads();
    // stage 3: lanes = (r = t, t+128); stored pairs along b2 -> repack
    #pragma unroll
    for (int uu = 0; uu < 8; ++uu){
        const ulonglong2 L = s2[t * S2R + uu];
        const ulonglong2 H = s2[(t + 128) * S2R + uu];
        re[2*uu]     = pklo(L.x, H.x);  im[2*uu]     = pklo(L.y, H.y);
        re[2*uu + 1] = pkhi(L.x, H.x);  im[2*uu + 1] = pkhi(L.y, H.y);
    }
    fft16_nat_p<-1>(re, im);     // over b2; F[256*d2 + r] at slot REV(d2)

    // ---- D scale (1/N folded), freq = 256*d2 + (t | t+128) ----
    #pragma unroll
    for (int d2 = 0; d2 < 16; ++d2){
        const float2 da = D2[256 * d2 + t];
        const float2 db = D2[256 * d2 + t + 128];
        const int s = REV(d2);
        re[s] = pmul(re[s], pk(da.x * INV_N, db.x * INV_N));
        im[s] = pmul(im[s], pk(da.y * INV_N, db.y * INV_N));
    }
    __syncthreads();   // stage-3 reads done before s1 overwrite (alias)

    // ================= inverse =================
    fft16_rev_p<1>(re, im);      // logical d2 at REV slot -> natural out
    twiddle_direct<0>(re, im, (float)t * D4096, (float)(t + 128) * D4096);
    #pragma unroll
    for (int c = 0; c < 16; ++c){
        s1[c * S1R + t] = make_ulonglong2(re[c], im[c]);   // pair = (r=t, r=t+128)
    }
    __syncthreads();
    // stage 2 inv: lanes = (b2 = u, u+8); stored pairs along a2 -> repack
    #pragma unroll
    for (int aa = 0; aa < 8; ++aa){
        const ulonglong2 L = s1[c1 * S1R + 16 * aa + u];
        const ulonglong2 H = s1[c1 * S1R + 16 * aa + u + 8];
        re[aa]     = pklo(L.x, H.x);  im[aa]     = pklo(L.y, H.y);
        re[aa + 8] = pkhi(L.x, H.x);  im[aa + 8] = pkhi(L.y, H.y);
    }
    fft16_nat_p<1>(re, im);
    twiddle_direct<1>(re, im, (float)u * D256, (float)(u + 8) * D256);
    __syncthreads();
    #pragma unroll
    for (int c2 = 0; c2 < 16; ++c2){
        s2[(16 * c2 + c1) * S2R + u] = make_ulonglong2(re[REV(c2)], im[REV(c2)]);
    }
    __syncthreads();
    // stage 3 inv: lanes = (m = t, t+128); stored pairs along b2 -> repack
    #pragma unroll
    for (int uu = 0; uu < 8; ++uu){
        const ulonglong2 L = s2[t * S2R + uu];
        const ulonglong2 H = s2[(t + 128) * S2R + uu];
        re[uu]     = pklo(L.x, H.x);  im[uu]     = pklo(L.y, H.y);
        re[uu + 8] = pkhi(L.x, H.x);  im[uu + 8] = pkhi(L.y, H.y);
    }
    fft16_nat_p<1>(re, im);      // over b2; out[256*d2 + m] at slot REV(d2)

    // ---- store ----
    #pragma unroll
    for (int d2 = 0; d2 < 16; ++d2){
        const int s = REV(d2);
        float r0, r1, i0, i1;
        unpk(re[s], r0, r1);
        unpk(im[s], i0, i1);
        out2[rb2 + 256 * d2 + t]       = make_float2(r0, i0);
        out2[rb2 + 256 * d2 + t + 128] = make_float2(r1, i1);
    }
}

extern "C" void kernel_launch(void* const* d_in, const int* in_sizes, int n_in,
                              void* d_out, int out_size)
{
    const float4* x4 = (const float4*)d_in[0];
    const float4* A4 = (const float4*)d_in[1];
    const float2* D2 = (const float2*)d_in[2];
    float2* out2 = (float2*)d_out;

    const int rows = in_sizes[0] / (4096 * 2);
    afdf_fft4_kernel<<<rows, 128>>>(x4, A4, D2, out2);
}

// round 5
// speedup vs baseline: 1.1653x; 1.1653x over previous
#include <cuda_runtime.h>
#include <cstdint>

// out = IFFT( D .* FFT( A .* x ) ) per row, C = 4096, complex as (re,im) float pairs.
// A, D scale re/im independently (elementwise).
//
// 128 threads per row; each thread carries TWO sub-FFT lanes as plain scalar
// floats (rA/iA, rB/iB). Complex multiplies in 4-instruction fma form.
// 4096 = 16^3: three radix-16 register stages; two shared exchanges per
// direction as float4{reA,reB,imA,imB} (16B STS/LDS, conflict-free strides
// 129 / 9). Twiddles via one __sincosf + odd/even power chains per stage.

#define REV(c) ((((c) & 3) << 2) | ((c) >> 2))

// complex multiply, 4 instrs: r' = fma(r,wr,-(i*wi)); i' = fma(r,wi,i*wr)
__device__ __forceinline__ void cmul(float& r, float& i, float wr, float wi){
    float t = i * wi;
    float u = i * wr;
    float nr = fmaf(r, wr, -t);
    i = fmaf(r, wi, u);
    r = nr;
}

// multiply by -i (DIR<0) / +i (DIR>0)
template<int DIR> __device__ __forceinline__ void mulj(float& r, float& i){
    float t = r;
    if (DIR < 0){ r = i;  i = -t; }
    else        { r = -i; i = t;  }
}
// constant twiddle: forward (cr, ci_f); inverse conjugate
template<int DIR> __device__ __forceinline__ void cmulc(float& r, float& i, float cr, float ci_f){
    cmul(r, i, cr, (DIR < 0) ? ci_f : -ci_f);
}

#define TC1 0.92387953251128674f
#define TS1 0.38268343236508978f
#define TC2 0.70710678118654752f

template<int DIR>
__device__ __forceinline__ void fft4s(float& r0, float& i0, float& r1, float& i1,
                                      float& r2, float& i2, float& r3, float& i3){
    float t0r = r0 + r2, t0i = i0 + i2;
    float t1r = r0 - r2, t1i = i0 - i2;
    float t2r = r1 + r3, t2i = i1 + i3;
    float t3r, t3i;
    if (DIR < 0){ t3r = i1 - i3; t3i = r3 - r1; }
    else        { t3r = i3 - i1; t3i = r1 - r3; }
    r0 = t0r + t2r; i0 = t0i + t2i;
    r2 = t0r - t2r; i2 = t0i - t2i;
    r1 = t1r + t3r; i1 = t1i + t3i;
    r3 = t1r - t3r; i3 = t1i - t3i;
}

// 16-point DFT, natural slots in -> output c at slot REV(c)
template<int DIR>
__device__ __forceinline__ void fft16_nat(float r[16], float i[16]){
    fft4s<DIR>(r[0],i[0], r[4],i[4], r[8], i[8],  r[12],i[12]);
    fft4s<DIR>(r[1],i[1], r[5],i[5], r[9], i[9],  r[13],i[13]);
    fft4s<DIR>(r[2],i[2], r[6],i[6], r[10],i[10], r[14],i[14]);
    fft4s<DIR>(r[3],i[3], r[7],i[7], r[11],i[11], r[15],i[15]);
    cmulc<DIR>(r[5], i[5],  TC1, -TS1);
    cmulc<DIR>(r[9], i[9],  TC2, -TC2);
    cmulc<DIR>(r[13],i[13], TS1, -TC1);
    cmulc<DIR>(r[6], i[6],  TC2, -TC2);
    mulj<DIR>(r[10],i[10]);
    cmulc<DIR>(r[14],i[14],-TC2, -TC2);
    cmulc<DIR>(r[7], i[7],  TS1, -TC1);
    cmulc<DIR>(r[11],i[11],-TC2, -TC2);
    cmulc<DIR>(r[15],i[15],-TC1,  TS1);
    fft4s<DIR>(r[0], i[0],  r[1], i[1],  r[2], i[2],  r[3], i[3]);
    fft4s<DIR>(r[4], i[4],  r[5], i[5],  r[6], i[6],  r[7], i[7]);
    fft4s<DIR>(r[8], i[8],  r[9], i[9],  r[10],i[10], r[11],i[11]);
    fft4s<DIR>(r[12],i[12], r[13],i[13], r[14],i[14], r[15],i[15]);
}

// 16-point DFT, input logical a at slot REV(a) -> natural output slots
template<int DIR>
__device__ __forceinline__ void fft16_rev(float r[16], float i[16]){
    fft4s<DIR>(r[0], i[0],  r[1], i[1],  r[2], i[2],  r[3], i[3]);
    fft4s<DIR>(r[4], i[4],  r[5], i[5],  r[6], i[6],  r[7], i[7]);
    fft4s<DIR>(r[8], i[8],  r[9], i[9],  r[10],i[10], r[11],i[11]);
    fft4s<DIR>(r[12],i[12], r[13],i[13], r[14],i[14], r[15],i[15]);
    cmulc<DIR>(r[5], i[5],  TC1, -TS1);
    cmulc<DIR>(r[6], i[6],  TC2, -TC2);
    cmulc<DIR>(r[7], i[7],  TS1, -TC1);
    cmulc<DIR>(r[9], i[9],  TC2, -TC2);
    mulj<DIR>(r[10],i[10]);
    cmulc<DIR>(r[11],i[11],-TC2, -TC2);
    cmulc<DIR>(r[13],i[13], TS1, -TC1);
    cmulc<DIR>(r[14],i[14],-TC2, -TC2);
    cmulc<DIR>(r[15],i[15],-TC1,  TS1);
    fft4s<DIR>(r[0],i[0], r[4],i[4], r[8], i[8],  r[12],i[12]);
    fft4s<DIR>(r[1],i[1], r[5],i[5], r[9], i[9],  r[13],i[13]);
    fft4s<DIR>(r[2],i[2], r[6],i[6], r[10],i[10], r[14],i[14]);
    fft4s<DIR>(r[3],i[3], r[7],i[7], r[11],i[11], r[15],i[15]);
}

// apply w^k to v[slot(k)], k=1..15; w = e^{DIR*i*theta}
template<int DIR, int RV>
__device__ __forceinline__ void twiddle_stage(float r[16], float i[16], float theta){
    float sn, cs;
    __sincosf(theta, &sn, &cs);
    if (DIR < 0) sn = -sn;
    float w2r = fmaf(cs, cs, -(sn * sn));
    float w2i = 2.0f * cs * sn;
    float por = cs,  poi = sn;    // odd powers
    float per = w2r, pei = w2i;   // even powers
    #pragma unroll
    for (int k = 1; k < 16; ++k){
        const int slot = RV ? REV(k) : k;
        if (k & 1){
            cmul(r[slot], i[slot], por, poi);
            if (k + 2 < 16) cmul(por, poi, w2r, w2i);
        } else {
            cmul(r[slot], i[slot], per, pei);
            if (k + 2 < 16) cmul(per, pei, w2r, w2i);
        }
    }
}

#define S1R 129   // entry stride (16B units); conflict-free for 128-bit LDS/STS
#define S2R 9
#define D4096 1.5339807878856412e-3f   // 2*pi/4096
#define D256  2.4543692606170259e-2f   // 2*pi/256
#define INV_N (1.0f / 4096.0f)

__global__ void __launch_bounds__(128, 4) afdf_fft5_kernel(
    const float4* __restrict__ x4,
    const float4* __restrict__ A4,
    const float2* __restrict__ D2,
    float2* __restrict__ out2)
{
    // shared scratch, reused: S1 = 16 rows x 129 entries; S2 = 256 rows x 9 entries
    // each entry = float4 {reA, reB, imA, imB}
    __shared__ float4 sb[256 * S2R];   // 2304 * 16B = 36,864 B

    const int t  = threadIdx.x;        // 0..127
    const int c1 = t & 15;
    const int u  = t >> 4;             // 0..7
    const size_t rb4 = (size_t)blockIdx.x * 2048;   // row base in float4 units
    const size_t rb2 = (size_t)blockIdx.x * 4096;   // row base in float2 units

    float rA[16], iA[16], rB[16], iB[16];

    // ---- load x, apply A; lanes = points m = (2t, 2t+1) ----
    #pragma unroll
    for (int a = 0; a < 16; ++a){
        const float4 xv = x4[rb4 + 128 * a + t];
        const float4 av = A4[128 * a + t];
        rA[a] = xv.x * av.x;  iA[a] = xv.y * av.y;
        rB[a] = xv.z * av.z;  iB[a] = xv.w * av.w;
    }

    // ================= forward =================
    fft16_nat<-1>(rA, iA);
    fft16_nat<-1>(rB, iB);
    twiddle_stage<-1, 1>(rA, iA, (float)(2*t)     * D4096);
    twiddle_stage<-1, 1>(rB, iB, (float)(2*t + 1) * D4096);
    #pragma unroll
    for (int c = 0; c < 16; ++c){
        const int s = REV(c);
        sb[c * S1R + t] = make_float4(rA[s], rB[s], iA[s], iB[s]);
    }
    __syncthreads();
    // stage 2: lanes = (b2 = 2u, 2u+1), iterate a2
    #pragma unroll
    for (int a2 = 0; a2 < 16; ++a2){
        const float4 v = sb[c1 * S1R + 8 * a2 + u];
        rA[a2] = v.x; rB[a2] = v.y; iA[a2] = v.z; iB[a2] = v.w;
    }
    fft16_nat<-1>(rA, iA);
    fft16_nat<-1>(rB, iB);
    twiddle_stage<-1, 1>(rA, iA, (float)(2*u)     * D256);
    twiddle_stage<-1, 1>(rB, iB, (float)(2*u + 1) * D256);
    __syncthreads();
    #pragma unroll
    for (int c2 = 0; c2 < 16; ++c2){
        const int s = REV(c2);
        sb[(16 * c2 + c1) * S2R + u] = make_float4(rA[s], rB[s], iA[s], iB[s]);
    }
    __syncthreads();
    // stage 3: lanes = (r = t, t+128); stored pairs along b2 -> rename
    #pragma unroll
    for (int uu = 0; uu < 8; ++uu){
        const float4 L = sb[t * S2R + uu];
        const float4 H = sb[(t + 128) * S2R + uu];
        rA[2*uu]   = L.x; iA[2*uu]   = L.z; rB[2*uu]   = H.x; iB[2*uu]   = H.z;
        rA[2*uu+1] = L.y; iA[2*uu+1] = L.w; rB[2*uu+1] = H.y; iB[2*uu+1] = H.w;
    }
    fft16_nat<-1>(rA, iA);
    fft16_nat<-1>(rB, iB);      // F[256*d2 + r] at slot REV(d2)

    // ---- D scale (1/N folded), freq = 256*d2 + (t | t+128) ----
    #pragma unroll
    for (int d2 = 0; d2 < 16; ++d2){
        const float2 da = D2[256 * d2 + t];
        const float2 db = D2[256 * d2 + t + 128];
        const int s = REV(d2);
        rA[s] *= da.x * INV_N;  iA[s] *= da.y * INV_N;
        rB[s] *= db.x * INV_N;  iB[s] *= db.y * INV_N;
    }
    __syncthreads();   // stage-3 reads complete before buffer reuse

    // ================= inverse =================
    fft16_rev<1>(rA, iA);
    fft16_rev<1>(rB, iB);
    twiddle_stage<1, 0>(rA, iA, (float)t * D4096);
    twiddle_stage<1, 0>(rB, iB, (float)(t + 128) * D4096);
    #pragma unroll
    for (int c = 0; c < 16; ++c){
        sb[c * S1R + t] = make_float4(rA[c], rB[c], iA[c], iB[c]);  // lanes (r=t, t+128)
    }
    __syncthreads();
    // stage 2 inv: lanes = (b2 = u, u+8); rename from (r, r+128) pairs
    #pragma unroll
    for (int aa = 0; aa < 8; ++aa){
        const float4 L = sb[c1 * S1R + 16 * aa + u];
        const float4 H = sb[c1 * S1R + 16 * aa + u + 8];
        rA[aa]   = L.x; iA[aa]   = L.z; rB[aa]   = H.x; iB[aa]   = H.z;
        rA[aa+8] = L.y; iA[aa+8] = L.w; rB[aa+8] = H.y; iB[aa+8] = H.w;
    }
    fft16_nat<1>(rA, iA);
    fft16_nat<1>(rB, iB);
    twiddle_stage<1, 1>(rA, iA, (float)u * D256);
    twiddle_stage<1, 1>(rB, iB, (float)(u + 8) * D256);
    __syncthreads();
    #pragma unroll
    for (int c2 = 0; c2 < 16; ++c2){
        const int s = REV(c2);
        sb[(16 * c2 + c1) * S2R + u] = make_float4(rA[s], rB[s], iA[s], iB[s]);
    }
    __syncthreads();
    // stage 3 inv: lanes = (m = t, t+128); rename
    #pragma unroll
    for (int uu = 0; uu < 8; ++uu){
        const float4 L = sb[t * S2R + uu];
        const float4 H = sb[(t + 128) * S2R + uu];
        rA[uu]   = L.x; iA[uu]   = L.z; rB[uu]   = H.x; iB[uu]   = H.z;
        rA[uu+8] = L.y; iA[uu+8] = L.w; rB[uu+8] = H.y; iB[uu+8] = H.w;
    }
    fft16_nat<1>(rA, iA);
    fft16_nat<1>(rB, iB);        // out[256*d2 + m] at slot REV(d2)

    // ---- store ----
    #pragma unroll
    for (int d2 = 0; d2 < 16; ++d2){
        const int s = REV(d2);
        out2[rb2 + 256 * d2 + t]       = make_float2(rA[s], iA[s]);
        out2[rb2 + 256 * d2 + t + 128] = make_float2(rB[s], iB[s]);
    }
}

extern "C" void kernel_launch(void* const* d_in, const int* in_sizes, int n_in,
                              void* d_out, int out_size)
{
    const float4* x4 = (const float4*)d_in[0];
    const float4* A4 = (const float4*)d_in[1];
    const float2* D2 = (const float2*)d_in[2];
    float2* out2 = (float2*)d_out;

    const int rows = in_sizes[0] / (4096 * 2);
    afdf_fft5_kernel<<<rows, 128>>>(x4, A4, D2, out2);
}